// round 1
// baseline (speedup 1.0000x reference)
#include <cuda_runtime.h>

// out[b, l, i, j] = emission[b, l, j] + transition[i, j]
// B=32, L=512, T=64. Output: 32*512*64*64 = 67,108,864 fp32 = 256 MB.
// Pure HBM-store-bound. One float4 (4 j's) per thread.
//
// Index decomposition of float4 index idx (total 16,777,216 float4s):
//   j4 = idx & 15         (16 float4s cover j=0..63)
//   i  = (idx >> 4) & 63
//   bl = idx >> 10        (b*L + l, 0..16383)

__global__ void CRF_53128745451552_kernel(const float4* __restrict__ em,
                                          const float4* __restrict__ tr,
                                          float4* __restrict__ out,
                                          int n4) {
    int idx = blockIdx.x * blockDim.x + threadIdx.x;
    if (idx >= n4) return;

    int j4 = idx & 15;
    int i  = (idx >> 4) & 63;
    int bl = idx >> 10;

    float4 e = __ldg(&em[(bl << 4) + j4]);   // emission[b,l, 4*j4 .. 4*j4+3]  (L1 broadcast)
    float4 t = __ldg(&tr[(i  << 4) + j4]);   // transition[i, 4*j4 .. 4*j4+3]  (16KB, L1-resident)

    float4 r;
    r.x = e.x + t.x;
    r.y = e.y + t.y;
    r.z = e.z + t.z;
    r.w = e.w + t.w;
    out[idx] = r;
}

extern "C" void kernel_launch(void* const* d_in, const int* in_sizes, int n_in,
                              void* d_out, int out_size) {
    const float4* em = (const float4*)d_in[0];   // emission [B, L, T] fp32
    const float4* tr = (const float4*)d_in[1];   // transition [T, T] fp32
    float4* out = (float4*)d_out;

    const int n4 = out_size / 4;                 // 16,777,216 float4 stores
    const int threads = 256;
    const int blocks = (n4 + threads - 1) / threads;
    CRF_53128745451552_kernel<<<blocks, threads>>>(em, tr, out, n4);
}

// round 2
// speedup vs baseline: 1.2334x; 1.2334x over previous
#include <cuda_runtime.h>

// out[b, l, i, j] = emission[b, l, j] + transition[i, j]
// B=32, L=512, T=64. Output = 256 MB fp32, pure HBM-write-bound.
//
// v8 (256-bit) unit decomposition: n8 = 8,388,608 float8 stores.
//   j8 = idx & 7        (8 float8 cover j=0..63)
//   i  = (idx >> 3) & 63
//   bl = idx >> 9
// Warp (32 lanes) covers 4 consecutive i rows => 1KB contiguous store span.
// Each thread does UNROLL=2 v8 stores (64 B), stores use .cs (evict-first).

#define UNROLL 2

__device__ __forceinline__ void ldg256(const float* p, float4& a, float4& b) {
    asm volatile("ld.global.nc.v8.f32 {%0,%1,%2,%3,%4,%5,%6,%7}, [%8];"
                 : "=f"(a.x), "=f"(a.y), "=f"(a.z), "=f"(a.w),
                   "=f"(b.x), "=f"(b.y), "=f"(b.z), "=f"(b.w)
                 : "l"(p));
}

__device__ __forceinline__ void stg256_cs(float* p, float4 a, float4 b) {
    asm volatile("st.global.cs.v8.f32 [%0], {%1,%2,%3,%4,%5,%6,%7,%8};"
                 :: "l"(p),
                    "f"(a.x), "f"(a.y), "f"(a.z), "f"(a.w),
                    "f"(b.x), "f"(b.y), "f"(b.z), "f"(b.w)
                 : "memory");
}

__global__ void CRF_53128745451552_kernel(const float* __restrict__ em,
                                          const float* __restrict__ tr,
                                          float* __restrict__ out) {
    // Each block handles UNROLL * blockDim.x consecutive v8 units.
    int base = blockIdx.x * (blockDim.x * UNROLL) + threadIdx.x;

#pragma unroll
    for (int u = 0; u < UNROLL; u++) {
        int idx = base + u * blockDim.x;     // v8-unit index
        int j8 = idx & 7;
        int i  = (idx >> 3) & 63;
        int bl = idx >> 9;

        float4 e0, e1, t0, t1;
        ldg256(em + ((size_t)bl << 6) + (j8 << 3), e0, e1);  // emission[bl, 8*j8..]
        ldg256(tr + (i << 6) + (j8 << 3), t0, t1);            // transition[i, 8*j8..]

        float4 r0, r1;
        r0.x = e0.x + t0.x;  r0.y = e0.y + t0.y;
        r0.z = e0.z + t0.z;  r0.w = e0.w + t0.w;
        r1.x = e1.x + t1.x;  r1.y = e1.y + t1.y;
        r1.z = e1.z + t1.z;  r1.w = e1.w + t1.w;

        stg256_cs(out + ((size_t)idx << 3), r0, r1);
    }
}

extern "C" void kernel_launch(void* const* d_in, const int* in_sizes, int n_in,
                              void* d_out, int out_size) {
    const float* em = (const float*)d_in[0];   // emission [32, 512, 64] fp32
    const float* tr = (const float*)d_in[1];   // transition [64, 64] fp32
    float* out = (float*)d_out;

    const int n8 = out_size / 8;               // 8,388,608 v8 units
    const int threads = 512;
    const int blocks = n8 / (threads * UNROLL);  // 8192 blocks, divides exactly
    CRF_53128745451552_kernel<<<blocks, threads>>>(em, tr, out);
}

// round 3
// speedup vs baseline: 1.3677x; 1.1089x over previous
#include <cuda_runtime.h>

// out[b, l, i, j] = emission[b, l, j] + transition[i, j]
// B=32, L=512, T=64. Output = 256 MB fp32, HBM-write-bound.
//
// One warp per (b,l) row (16384 warps total).
// Lane decomposition: j8 = lane & 7 (which 8-float j chunk), igrp = lane >> 3.
// Emission chunk loaded ONCE per lane into registers; 16 iterations over
// i = it*4 + igrp cover all 64 transition rows. Each warp-iteration stores
// 1 KB contiguous. Transition (16 KB) is L1-resident after warmup.

__device__ __forceinline__ void ldg256(const float* p, float4& a, float4& b) {
    asm volatile("ld.global.nc.v8.f32 {%0,%1,%2,%3,%4,%5,%6,%7}, [%8];"
                 : "=f"(a.x), "=f"(a.y), "=f"(a.z), "=f"(a.w),
                   "=f"(b.x), "=f"(b.y), "=f"(b.z), "=f"(b.w)
                 : "l"(p));
}

__device__ __forceinline__ void stg256_cs(float* p, float4 a, float4 b) {
    asm volatile("st.global.cs.v8.f32 [%0], {%1,%2,%3,%4,%5,%6,%7,%8};"
                 :: "l"(p),
                    "f"(a.x), "f"(a.y), "f"(a.z), "f"(a.w),
                    "f"(b.x), "f"(b.y), "f"(b.z), "f"(b.w)
                 : "memory");
}

__global__ void CRF_53128745451552_kernel(const float* __restrict__ em,
                                          const float* __restrict__ tr,
                                          float* __restrict__ out) {
    int warp = (blockIdx.x * blockDim.x + threadIdx.x) >> 5;  // = bl, 0..16383
    int lane = threadIdx.x & 31;
    int j8   = lane & 7;    // 8-float chunk within j (0..7)
    int igrp = lane >> 3;   // i offset within a 4-row group (0..3)

    // Emission chunk for this (bl, j8): loaded once, reused 16x.
    float4 e0, e1;
    ldg256(em + ((size_t)warp << 6) + (j8 << 3), e0, e1);

    const float* tp = tr  + (igrp << 6) + (j8 << 3);
    float*       op = out + ((size_t)warp << 12) + (igrp << 6) + (j8 << 3);

#pragma unroll 4
    for (int it = 0; it < 16; it++) {
        float4 t0, t1;
        ldg256(tp + it * 256, t0, t1);   // transition[it*4+igrp, j8*8..] (L1 hit)

        float4 r0, r1;
        r0.x = e0.x + t0.x;  r0.y = e0.y + t0.y;
        r0.z = e0.z + t0.z;  r0.w = e0.w + t0.w;
        r1.x = e1.x + t1.x;  r1.y = e1.y + t1.y;
        r1.z = e1.z + t1.z;  r1.w = e1.w + t1.w;

        stg256_cs(op + it * 256, r0, r1);  // warp-iter: 1KB contiguous
    }
}

extern "C" void kernel_launch(void* const* d_in, const int* in_sizes, int n_in,
                              void* d_out, int out_size) {
    const float* em = (const float*)d_in[0];   // emission [32, 512, 64] fp32
    const float* tr = (const float*)d_in[1];   // transition [64, 64] fp32
    float* out = (float*)d_out;

    // 16384 rows, one warp each; 256 threads = 8 warps per block.
    const int threads = 256;
    const int blocks  = 16384 / 8;   // 2048
    CRF_53128745451552_kernel<<<blocks, threads>>>(em, tr, out);
}